// round 13
// baseline (speedup 1.0000x reference)
#include <cuda_runtime.h>

// BoxRenderLoss, single fused launch, R13.
//
// Separable boundary-min (4 edges x 25 linspace samples):
//   min over {X0,X1}x{y_k}  = min((px-X0)^2,(px-X1)^2) + min_k (py-y_k)^2
//   min over {x_k}x{Y0,Y1}  = min((py-Y0)^2,(py-Y1)^2) + min_k (px-x_k)^2
// Nearest-sample window {k, k+1}, k = magic_round(tcc - 0.5); all-float.
//
// R13: revert to the confirmed-optimal 160 blocks x 512 threads (R11,
// 5.79us; 80x1024 regressed to 6.21 - SM under-use + fat block barrier).
// Keep R12's orthogonal wins:
//   * t = dr*4096 + b indexing: b = AND, dr = SHR -> LDG address ready
//     cycles earlier; boxes[b]/targets[b] perfectly coalesced per warp.
//   * cross-warp tail: warp 0 reduces 16 partials with 4 s64 shuffles
//     instead of a serial 16-add loop on thread 0.
// Tail: ONE packed u64 atomicAdd per block (low 54 bits: 2^21 fixed-point
// sum, high 10: arrival count; return value hands the last block the
// complete sum). Integer accumulation -> bitwise deterministic.

#define THREADS 512
#define WARPS   (THREADS / 32)
#define FIX_SCALE 2097152.0f              // 2^21
#define INV_FIX   (1.0f / 2097152.0f)
#define CNT_ONE (1ull << 54)              // counter increment (bits 54..63)

__device__ unsigned long long g_acc = 0ull;   // zero-init; last block resets

// min over k=0..24 of (p - (k*(1/24)*len + lo))^2, matching reference
// sampling (s_k = fmaf(k*(1/24), len, lo)). inv24len = 24/len precomputed.
__device__ __forceinline__ float edge_min_sq(float p, float lo, float len,
                                             float inv24len) {
    const float DB    = 1.0f / 24.0f;
    const float MAGIC = 12582912.0f;               // 1.5 * 2^23
    float tc = (p - lo) * inv24len;                // continuous nearest index
    // NaN/inf-safe clamp (len==0 -> tc inf/NaN -> clamps into range)
    float tcc = fminf(fmaxf(tc, 0.0f), 24.0f);
    // k in [max(0,floor-1), floor]; probes {k, k+1} bracket the nearest sample
    float k0 = ((tcc - 0.5f) + MAGIC) - MAGIC;
    float k1 = fminf(k0 + 1.0f, 24.0f);

    float s0 = fmaf(k0 * DB, len, lo);             // same formula as reference
    float s1 = fmaf(k1 * DB, len, lo);
    float d0 = p - s0, d1 = p - s1;
    return fminf(d0 * d0, d1 * d1);
}

__global__ __launch_bounds__(THREADS)
void box_render_loss_fused(const float4* __restrict__ boxes,
                           const float4* __restrict__ targets,
                           float* __restrict__ out,
                           float scale_out, unsigned int nblocks) {
    int t = blockIdx.x * THREADS + threadIdx.x;   // in [0, 20*4096)

    // task layout: t = dr*4096 + b, dr in [0,20), b in [0,4096)
    int b  = t & 4095;          // pair index (AND) -> coalesced loads
    int dr = t >> 12;           // (direction,row) in [0,20) (SHIFT)
    int d   = (dr >= 10) ? 1 : 0;
    int row = dr - d * 10;      // fragment row -> px

    float4 A = boxes[b];
    float4 T = targets[b];
    float4 F = d ? T : A;       // fragment-source box
    float4 O = d ? A : T;       // other box

    const float DF = 1.0f / 9.0f;
    float fw = F.z - F.x, fh = F.w - F.y;
    float px = fmaf((float)row * DF, fw, F.x);

    float ow = O.z - O.x, oh = O.w - O.y;
    float inv24w = 24.0f * __frcp_rn(ow);
    float inv24h = 24.0f * __frcp_rn(oh);
    float X1 = ow + O.x;        // 1*ow + O.x, exactly as reference computes it
    float Y1 = oh + O.y;

    // x-dependent terms, hoisted across the 10 py values
    bool in_x   = (px - O.x >= 0.0f) && (O.z - px >= 0.0f);
    float dx0 = px - O.x, dx1 = px - X1;
    float vert_x = fminf(dx0 * dx0, dx1 * dx1);        // vertical edges, x part
    float dxmin  = edge_min_sq(px, O.x, ow, inv24w);   // horizontal edges, x part

    float val = 0.0f;
    float fi = 0.0f;
#pragma unroll
    for (int j = 0; j < 10; ++j) {
        float py = fmaf(fi * DF, fh, F.y);
        fi += 1.0f;
        bool inside = in_x && (py - O.y >= 0.0f) && (O.w - py >= 0.0f);
        if (!inside) {
            float dymin = edge_min_sq(py, O.y, oh, inv24h);
            float dy0 = py - O.y, dy1 = py - Y1;
            float horz = fminf(dy0 * dy0, dy1 * dy1) + dxmin;
            val += fminf(vert_x + dymin, horz);
        }
    }

    // fixed-point warp reduction, exact integers -> deterministic.
    // val <= 20 (coords in [0,1] -> dist^2 <= 2, 10 fragments);
    // warp sum <= 32*20*2^21 = 1.34e9 < 2^31: provably no overflow.
    int q = __float2int_rn(val * FIX_SCALE);
    int wsum = __reduce_add_sync(0xffffffffu, q);

    __shared__ int ws[WARPS];
    int lane = threadIdx.x & 31;
    int wid  = threadIdx.x >> 5;
    if (lane == 0) ws[wid] = wsum;
    __syncthreads();

    if (wid == 0) {
        // warp 0: 16 partials -> 4 s64 shuffles (block sum can exceed s32)
        long long v64 = (lane < WARPS) ? (long long)ws[lane] : 0ll;
#pragma unroll
        for (int o = WARPS / 2; o > 0; o >>= 1)
            v64 += __shfl_down_sync(0xffffffffu, v64, o);

        if (lane == 0) {
            // one packed atomic: low 54 bits = 2^21 fixed-point sum (integer,
            // order-independent -> deterministic), high 10 bits = count.
            unsigned long long pq = (unsigned long long)v64 + CNT_ONE;
            unsigned long long old = atomicAdd(&g_acc, pq);
            if ((old >> 54) == (unsigned long long)(nblocks - 1u)) {
                // last arrival: old + pq is the complete packed value
                unsigned long long total = (old + pq) & (CNT_ONE - 1ull);
                out[0] = (float)total * scale_out;   // rel err ~2^-24, fine
                g_acc = 0ull;   // no competing writers; kernel-end orders it
            }
        }
    }
}

extern "C" void kernel_launch(void* const* d_in, const int* in_sizes, int n_in,
                              void* d_out, int out_size) {
    const float4* boxes   = (const float4*)d_in[0];
    const float4* targets = (const float4*)d_in[1];
    float* out = (float*)d_out;

    int B = in_sizes[0] / 4;                 // 4096
    int ntasks = B * 20;                     // 2 directions * 10 rows
    unsigned int nblocks = (unsigned int)(ntasks / THREADS);  // 160, exact

    // (1 / (2*B*100)) * 2^-21  (undo fixed point), applied in f32
    float scale_out = (float)(1.0 / (2.0 * (double)B * 100.0) * (double)INV_FIX);

    box_render_loss_fused<<<nblocks, THREADS>>>(boxes, targets, out,
                                                scale_out, nblocks);
}

// round 14
// speedup vs baseline: 1.0037x; 1.0037x over previous
#include <cuda_runtime.h>

// BoxRenderLoss, single fused launch, R14.
//
// Separable boundary-min (4 edges x 25 linspace samples):
//   min over {X0,X1}x{y_k}  = min((px-X0)^2,(px-X1)^2) + min_k (py-y_k)^2
//   min over {x_k}x{Y0,Y1}  = min((py-Y0)^2,(py-Y1)^2) + min_k (px-x_k)^2
// Nearest-sample window {k, k+1}, k = magic_round(tcc - 0.5); all-float.
//
// R14 = R11 champion shape (160 blocks x 512 thr, b = t/20 indexing: 20
// consecutive threads share a box pair -> warp loads are near-broadcast,
// ~2 cache lines per array per warp) + bar-free tail:
//   * thread 0 zeroes a smem u64 accumulator; the ONLY barrier is at the
//     top (zero warp skew there, ~10 cyc).
//   * each warp: REDUX int sum -> lane0 smem atomicAdd(sum + 1<<40).
//     The warp seeing count==WARPS-1 in the RETURN VALUE owns the block
//     total and immediately issues the global packed atomic. No end bar,
//     no cross-warp shuffle chain on the gating path.
// Global tail: ONE packed u64 atomicAdd per block (low 54: 2^21 fixed-point
// sum, high 10: arrival count; return value hands the last block the grid
// total). Integer accumulation -> bitwise deterministic.

#define THREADS 512
#define WARPS   (THREADS / 32)
#define FIX_SCALE 2097152.0f              // 2^21
#define INV_FIX   (1.0f / 2097152.0f)
#define WCNT_ONE (1ull << 40)             // smem warp-arrival counter bit
#define CNT_ONE  (1ull << 54)             // global block-arrival counter bit

__device__ unsigned long long g_acc = 0ull;   // zero-init; last block resets

// min over k=0..24 of (p - (k*(1/24)*len + lo))^2, matching reference
// sampling (s_k = fmaf(k*(1/24), len, lo)). inv24len = 24/len precomputed.
__device__ __forceinline__ float edge_min_sq(float p, float lo, float len,
                                             float inv24len) {
    const float DB    = 1.0f / 24.0f;
    const float MAGIC = 12582912.0f;               // 1.5 * 2^23
    float tc = (p - lo) * inv24len;                // continuous nearest index
    // NaN/inf-safe clamp (len==0 -> tc inf/NaN -> clamps into range)
    float tcc = fminf(fmaxf(tc, 0.0f), 24.0f);
    // k in [max(0,floor-1), floor]; probes {k, k+1} bracket the nearest sample
    float k0 = ((tcc - 0.5f) + MAGIC) - MAGIC;
    float k1 = fminf(k0 + 1.0f, 24.0f);

    float s0 = fmaf(k0 * DB, len, lo);             // same formula as reference
    float s1 = fmaf(k1 * DB, len, lo);
    float d0 = p - s0, d1 = p - s1;
    return fminf(d0 * d0, d1 * d1);
}

__global__ __launch_bounds__(THREADS)
void box_render_loss_fused(const float4* __restrict__ boxes,
                           const float4* __restrict__ targets,
                           float* __restrict__ out,
                           float scale_out, unsigned int nblocks) {
    __shared__ unsigned long long s_acc;
    if (threadIdx.x == 0) s_acc = 0ull;
    __syncthreads();                 // top-of-kernel: zero skew, cheap

    int t = blockIdx.x * THREADS + threadIdx.x;   // grid*block == ntasks

    int row = t % 10;           // fragment row -> px
    int d   = (t / 10) & 1;     // direction: 0 = box frags vs target, 1 = swap
    int b   = t / 20;           // pair index: 20 threads share b -> broadcast

    float4 A = boxes[b];
    float4 T = targets[b];
    float4 F = d ? T : A;       // fragment-source box
    float4 O = d ? A : T;       // other box

    const float DF = 1.0f / 9.0f;
    float fw = F.z - F.x, fh = F.w - F.y;
    float px = fmaf((float)row * DF, fw, F.x);

    float ow = O.z - O.x, oh = O.w - O.y;
    float inv24w = 24.0f * __frcp_rn(ow);
    float inv24h = 24.0f * __frcp_rn(oh);
    float X1 = ow + O.x;        // 1*ow + O.x, exactly as reference computes it
    float Y1 = oh + O.y;

    // x-dependent terms, hoisted across the 10 py values
    bool in_x   = (px - O.x >= 0.0f) && (O.z - px >= 0.0f);
    float dx0 = px - O.x, dx1 = px - X1;
    float vert_x = fminf(dx0 * dx0, dx1 * dx1);        // vertical edges, x part
    float dxmin  = edge_min_sq(px, O.x, ow, inv24w);   // horizontal edges, x part

    float val = 0.0f;
    float fi = 0.0f;
#pragma unroll
    for (int j = 0; j < 10; ++j) {
        float py = fmaf(fi * DF, fh, F.y);
        fi += 1.0f;
        bool inside = in_x && (py - O.y >= 0.0f) && (O.w - py >= 0.0f);
        if (!inside) {
            float dymin = edge_min_sq(py, O.y, oh, inv24h);
            float dy0 = py - O.y, dy1 = py - Y1;
            float horz = fminf(dy0 * dy0, dy1 * dy1) + dxmin;
            val += fminf(vert_x + dymin, horz);
        }
    }

    // fixed-point warp reduction, exact integers -> deterministic.
    // val <= 20 -> q <= 20*2^21; warp sum <= 32*20*2^21 = 1.34e9 < 2^31.
    int q = __float2int_rn(val * FIX_SCALE);
    int wsum = __reduce_add_sync(0xffffffffu, q);

    if ((threadIdx.x & 31) == 0) {
        // smem packed accumulator: low 40 bits sum (block sum <= 512*20*2^21
        // = 2.1e10 < 2^40 worst-case... 2.147e10 < 2^35? no: < 2^35 is 3.4e10,
        // so sum < 2^35 << 2^40, safe), bits 40+ = warp arrival count.
        unsigned long long wq = (unsigned long long)(unsigned int)wsum + WCNT_ONE;
        unsigned long long wold = atomicAdd(&s_acc, wq);
        if ((wold >> 40) == (unsigned long long)(WARPS - 1)) {
            // last warp of this block: owns the complete block sum
            unsigned long long bsum = (wold + wq) & (WCNT_ONE - 1ull);
            // global packed atomic: low 54 sum, high 10 block count
            unsigned long long pq = bsum + CNT_ONE;
            unsigned long long old = atomicAdd(&g_acc, pq);
            if ((old >> 54) == (unsigned long long)(nblocks - 1u)) {
                unsigned long long total = (old + pq) & (CNT_ONE - 1ull);
                out[0] = (float)total * scale_out;   // rel err ~2^-24, fine
                g_acc = 0ull;   // no competing writers; kernel-end orders it
            }
        }
    }
}

extern "C" void kernel_launch(void* const* d_in, const int* in_sizes, int n_in,
                              void* d_out, int out_size) {
    const float4* boxes   = (const float4*)d_in[0];
    const float4* targets = (const float4*)d_in[1];
    float* out = (float*)d_out;

    int B = in_sizes[0] / 4;                 // 4096
    int ntasks = B * 20;                     // 2 directions * 10 rows
    unsigned int nblocks = (unsigned int)(ntasks / THREADS);  // 160, exact

    // (1 / (2*B*100)) * 2^-21  (undo fixed point), applied in f32
    float scale_out = (float)(1.0 / (2.0 * (double)B * 100.0) * (double)INV_FIX);

    box_render_loss_fused<<<nblocks, THREADS>>>(boxes, targets, out,
                                                scale_out, nblocks);
}

// round 15
// speedup vs baseline: 1.0342x; 1.0304x over previous
#include <cuda_runtime.h>

// BoxRenderLoss, single fused launch, R15.
//
// Separable boundary-min (4 edges x 25 linspace samples):
//   min over {X0,X1}x{y_k}  = min((px-X0)^2,(px-X1)^2) + min_k (py-y_k)^2
//   min over {x_k}x{Y0,Y1}  = min((py-Y0)^2,(py-Y1)^2) + min_k (px-x_k)^2
// Nearest-sample window {k, k+1}, k = magic_round(tcc - 0.5); all-float.
//
// R15: decouple R12's confound. 80 blocks x 512 threads (proven-cheap
// block size), TWO tasks per thread (t and t+40960; b = t/20 broadcast
// mapping kept; both tasks' loads in flight together -> MLP 2).
// Burst 160 -> 80 atomics, CTA ramp halves. Fixed point 2^20 so the
// worst-case warp sum (32 thr x 2 tasks x 20) provably fits s32.
// Tail (R11 style, measured best): REDUX warp sum -> smem -> barrier ->
// thread0 serial add -> ONE packed u64 global atomic per block
// (low 54: sum, high 10: arrival count; return value hands the last
// block the grid total). Integer accumulation -> deterministic.

#define THREADS 512
#define WARPS   (THREADS / 32)
#define FIX_SCALE 1048576.0f              // 2^20
#define INV_FIX   (1.0f / 1048576.0f)
#define CNT_ONE (1ull << 54)              // global block-arrival counter bit

__device__ unsigned long long g_acc = 0ull;   // zero-init; last block resets

// min over k=0..24 of (p - (k*(1/24)*len + lo))^2, matching reference
// sampling (s_k = fmaf(k*(1/24), len, lo)). inv24len = 24/len precomputed.
__device__ __forceinline__ float edge_min_sq(float p, float lo, float len,
                                             float inv24len) {
    const float DB    = 1.0f / 24.0f;
    const float MAGIC = 12582912.0f;               // 1.5 * 2^23
    float tc = (p - lo) * inv24len;                // continuous nearest index
    // NaN/inf-safe clamp (len==0 -> tc inf/NaN -> clamps into range)
    float tcc = fminf(fmaxf(tc, 0.0f), 24.0f);
    // k in [max(0,floor-1), floor]; probes {k, k+1} bracket the nearest sample
    float k0 = ((tcc - 0.5f) + MAGIC) - MAGIC;
    float k1 = fminf(k0 + 1.0f, 24.0f);

    float s0 = fmaf(k0 * DB, len, lo);             // same formula as reference
    float s1 = fmaf(k1 * DB, len, lo);
    float d0 = p - s0, d1 = p - s1;
    return fminf(d0 * d0, d1 * d1);
}

// one (b, d, row) task: 10 fragments of a row vs the other box
__device__ __forceinline__ float task_sum(const float4* __restrict__ boxes,
                                          const float4* __restrict__ targets,
                                          int t) {
    int row = t % 10;           // fragment row -> px
    int d   = (t / 10) & 1;     // direction: 0 = box frags vs target, 1 = swap
    int b   = t / 20;           // pair index: 20 threads share b -> broadcast

    float4 A = boxes[b];
    float4 T = targets[b];
    float4 F = d ? T : A;       // fragment-source box
    float4 O = d ? A : T;       // other box

    const float DF = 1.0f / 9.0f;
    float fw = F.z - F.x, fh = F.w - F.y;
    float px = fmaf((float)row * DF, fw, F.x);

    float ow = O.z - O.x, oh = O.w - O.y;
    float inv24w = 24.0f * __frcp_rn(ow);
    float inv24h = 24.0f * __frcp_rn(oh);
    float X1 = ow + O.x;        // 1*ow + O.x, exactly as reference computes it
    float Y1 = oh + O.y;

    // x-dependent terms, hoisted across the 10 py values
    bool in_x   = (px - O.x >= 0.0f) && (O.z - px >= 0.0f);
    float dx0 = px - O.x, dx1 = px - X1;
    float vert_x = fminf(dx0 * dx0, dx1 * dx1);        // vertical edges, x part
    float dxmin  = edge_min_sq(px, O.x, ow, inv24w);   // horizontal edges, x part

    float val = 0.0f;
    float fi = 0.0f;
#pragma unroll
    for (int j = 0; j < 10; ++j) {
        float py = fmaf(fi * DF, fh, F.y);
        fi += 1.0f;
        bool inside = in_x && (py - O.y >= 0.0f) && (O.w - py >= 0.0f);
        if (!inside) {
            float dymin = edge_min_sq(py, O.y, oh, inv24h);
            float dy0 = py - O.y, dy1 = py - Y1;
            float horz = fminf(dy0 * dy0, dy1 * dy1) + dxmin;
            val += fminf(vert_x + dymin, horz);
        }
    }
    return val;
}

__global__ __launch_bounds__(THREADS)
void box_render_loss_fused(const float4* __restrict__ boxes,
                           const float4* __restrict__ targets,
                           float* __restrict__ out,
                           float scale_out, unsigned int nblocks, int half) {
    int t = blockIdx.x * THREADS + threadIdx.x;   // in [0, half)

    // two independent tasks -> loads of both issue early, MLP=2
    float val = task_sum(boxes, targets, t) +
                task_sum(boxes, targets, t + half);

    // fixed-point warp reduction, exact integers -> deterministic.
    // val <= 40 -> q <= 40*2^20; warp sum <= 32*40*2^20 = 1.34e9 < 2^31.
    int q = __float2int_rn(val * FIX_SCALE);
    int wsum = __reduce_add_sync(0xffffffffu, q);

    __shared__ int ws[WARPS];
    int lane = threadIdx.x & 31;
    int wid  = threadIdx.x >> 5;
    if (lane == 0) ws[wid] = wsum;
    __syncthreads();

    if (threadIdx.x == 0) {
        long long bsum = 0;
#pragma unroll
        for (int w = 0; w < WARPS; ++w)
            bsum += (long long)ws[w];

        // one packed atomic: low 54 bits = 2^20 fixed-point sum (integer,
        // order-independent -> deterministic), high 10 bits = count.
        unsigned long long pq = (unsigned long long)bsum + CNT_ONE;
        unsigned long long old = atomicAdd(&g_acc, pq);
        if ((old >> 54) == (unsigned long long)(nblocks - 1u)) {
            // last arrival: old + pq is the complete packed value
            unsigned long long total = (old + pq) & (CNT_ONE - 1ull);
            out[0] = (float)total * scale_out;   // rel err ~2^-24, fine
            g_acc = 0ull;   // no competing writers; kernel-end orders it
        }
    }
}

extern "C" void kernel_launch(void* const* d_in, const int* in_sizes, int n_in,
                              void* d_out, int out_size) {
    const float4* boxes   = (const float4*)d_in[0];
    const float4* targets = (const float4*)d_in[1];
    float* out = (float*)d_out;

    int B = in_sizes[0] / 4;                 // 4096
    int ntasks = B * 20;                     // 81920
    int half = ntasks / 2;                   // 40960
    unsigned int nblocks = (unsigned int)(half / THREADS);   // 80, exact

    // (1 / (2*B*100)) * 2^-20  (undo fixed point), applied in f32
    float scale_out = (float)(1.0 / (2.0 * (double)B * 100.0) * (double)INV_FIX);

    box_render_loss_fused<<<nblocks, THREADS>>>(boxes, targets, out,
                                                scale_out, nblocks, half);
}

// round 16
// speedup vs baseline: 1.2420x; 1.2009x over previous
#include <cuda_runtime.h>

// BoxRenderLoss, single fused launch — FINAL (R11 champion, kernel 5.79us).
//
// Algorithm: the 100 boundary points of a box are 4 axis-aligned edges x 25
// evenly spaced samples, so min squared distance separates per axis:
//   min over {X0,X1}x{y_k}  = min((px-X0)^2,(px-X1)^2) + min_k (py-y_k)^2
//   min over {x_k}x{Y0,Y1}  = min((py-Y0)^2,(py-Y1)^2) + min_k (px-x_k)^2
// Nearest-sample window {k, k+1}, k = magic_round(tcc - 0.5), computed
// entirely in float (no F2I/I2F on the hot path); sample values use the
// same fmaf(k*(1/24), len, lo) formula as the reference -> rel_err 0.
//
// Measured shape optimum: 160 blocks x 512 threads, one (b,d,row) task per
// thread, b = t/20 (20 consecutive threads share a box pair -> near-
// broadcast warp loads, ~2 cache lines per array per warp).
// Tail: REDUX.SUM fixed-point warp reduce (2^22 units, exact integers ->
// bitwise deterministic) -> smem -> barrier -> thread0 serial add -> ONE
// packed u64 global atomicAdd per block (low 54 bits: sum, high 10 bits:
// arrival counter; the atomic's RETURN VALUE hands the last-arriving block
// the complete grid sum -> single round-trip tail, self-resetting for
// graph replay).

#define THREADS 512
#define WARPS   (THREADS / 32)
#define FIX_SCALE 4194304.0f              // 2^22
#define INV_FIX   (1.0f / 4194304.0f)
#define CNT_ONE (1ull << 54)              // counter increment (bits 54..63)

__device__ unsigned long long g_acc = 0ull;   // zero-init; last block resets

// min over k=0..24 of (p - (k*(1/24)*len + lo))^2, matching reference
// sampling (s_k = fmaf(k*(1/24), len, lo)). inv24len = 24/len precomputed.
__device__ __forceinline__ float edge_min_sq(float p, float lo, float len,
                                             float inv24len) {
    const float DB    = 1.0f / 24.0f;
    const float MAGIC = 12582912.0f;               // 1.5 * 2^23
    float tc = (p - lo) * inv24len;                // continuous nearest index
    // NaN/inf-safe clamp (len==0 -> tc inf/NaN -> clamps into range)
    float tcc = fminf(fmaxf(tc, 0.0f), 24.0f);
    // k in [max(0,floor-1), floor]; probes {k, k+1} bracket the nearest sample
    float k0 = ((tcc - 0.5f) + MAGIC) - MAGIC;
    float k1 = fminf(k0 + 1.0f, 24.0f);

    float s0 = fmaf(k0 * DB, len, lo);             // same formula as reference
    float s1 = fmaf(k1 * DB, len, lo);
    float d0 = p - s0, d1 = p - s1;
    return fminf(d0 * d0, d1 * d1);
}

__global__ __launch_bounds__(THREADS)
void box_render_loss_fused(const float4* __restrict__ boxes,
                           const float4* __restrict__ targets,
                           float* __restrict__ out,
                           float scale_out, unsigned int nblocks) {
    int t = blockIdx.x * THREADS + threadIdx.x;   // grid*block == ntasks

    int row = t % 10;           // fragment row -> px
    int d   = (t / 10) & 1;     // direction: 0 = box frags vs target, 1 = swap
    int b   = t / 20;           // pair index: 20 threads share b -> broadcast

    float4 A = boxes[b];
    float4 T = targets[b];
    float4 F = d ? T : A;       // fragment-source box
    float4 O = d ? A : T;       // other box

    const float DF = 1.0f / 9.0f;
    float fw = F.z - F.x, fh = F.w - F.y;
    float px = fmaf((float)row * DF, fw, F.x);

    float ow = O.z - O.x, oh = O.w - O.y;
    float inv24w = 24.0f * __frcp_rn(ow);
    float inv24h = 24.0f * __frcp_rn(oh);
    float X1 = ow + O.x;        // 1*ow + O.x, exactly as reference computes it
    float Y1 = oh + O.y;

    // x-dependent terms, hoisted across the 10 py values
    bool in_x   = (px - O.x >= 0.0f) && (O.z - px >= 0.0f);
    float dx0 = px - O.x, dx1 = px - X1;
    float vert_x = fminf(dx0 * dx0, dx1 * dx1);        // vertical edges, x part
    float dxmin  = edge_min_sq(px, O.x, ow, inv24w);   // horizontal edges, x part

    float val = 0.0f;
    float fi = 0.0f;
#pragma unroll
    for (int j = 0; j < 10; ++j) {
        float py = fmaf(fi * DF, fh, F.y);
        fi += 1.0f;
        bool inside = in_x && (py - O.y >= 0.0f) && (O.w - py >= 0.0f);
        if (!inside) {
            float dymin = edge_min_sq(py, O.y, oh, inv24h);
            float dy0 = py - O.y, dy1 = py - Y1;
            float horz = fminf(dy0 * dy0, dy1 * dy1) + dxmin;
            val += fminf(vert_x + dymin, horz);
        }
    }

    // fixed-point warp reduction: exact integer adds -> deterministic.
    // val in [0, 20] -> q <= 20*2^22; warp sum <= 640*2^22 < 2^31.
    int q = __float2int_rn(val * FIX_SCALE);
    int wsum = __reduce_add_sync(0xffffffffu, q);

    __shared__ int ws[WARPS];
    int lane = threadIdx.x & 31;
    int wid  = threadIdx.x >> 5;
    if (lane == 0) ws[wid] = wsum;
    __syncthreads();

    if (threadIdx.x == 0) {
        long long bsum = 0;
#pragma unroll
        for (int w = 0; w < WARPS; ++w)
            bsum += (long long)ws[w];

        // one packed atomic: low 54 bits = 2^22 fixed-point sum (integer,
        // order-independent -> deterministic), high 10 bits = arrival count.
        unsigned long long pq = (unsigned long long)bsum + CNT_ONE;
        unsigned long long old = atomicAdd(&g_acc, pq);
        if ((old >> 54) == (unsigned long long)(nblocks - 1u)) {
            // last arrival: old + pq is the complete packed value
            unsigned long long total = (old + pq) & (CNT_ONE - 1ull);
            out[0] = (float)total * scale_out;   // rel err ~2^-24, fine
            g_acc = 0ull;   // no competing writers remain; kernel-end orders it
        }
    }
}

extern "C" void kernel_launch(void* const* d_in, const int* in_sizes, int n_in,
                              void* d_out, int out_size) {
    const float4* boxes   = (const float4*)d_in[0];
    const float4* targets = (const float4*)d_in[1];
    float* out = (float*)d_out;

    int B = in_sizes[0] / 4;                 // 4096
    int ntasks = B * 20;                     // 2 directions * 10 rows
    unsigned int nblocks = (unsigned int)(ntasks / THREADS);  // 160, exact

    // (1 / (2*B*100)) * 2^-22  (undo fixed point), applied in f32
    float scale_out = (float)(1.0 / (2.0 * (double)B * 100.0) * (double)INV_FIX);

    box_render_loss_fused<<<nblocks, THREADS>>>(boxes, targets, out,
                                                scale_out, nblocks);
}